// round 9
// baseline (speedup 1.0000x reference)
#include <cuda_runtime.h>
#include <cuda_fp16.h>
#include <cstdint>

#define NNODES 50000
#define NEDGES 800000
#define ETOT   (NNODES + NEDGES)
#define HEADS  4
#define HID    64
#define HH     256   // HEADS*HID
#define INC    128
#define OUTC   128
#define NCHUNK ((NNODES + 1023) / 1024)

// ---------------- scratch (device globals; no allocation) ----------------
__device__ __half g_H [NNODES * HH];      // transformed features, fp16 [N,4,64]
__device__ float g_ES  [NNODES * HEADS];
__device__ float g_ED  [NNODES * HEADS];
__device__ float g_F1  [NNODES * HID];
__device__ float g_F2  [NNODES * HID];
__device__ float g_WSD1[INC * 8];
__device__ float g_WSD2[HID * 8];
__device__ __half g_W4 [(size_t)ETOT * HEADS];   // per-edge weights (fp16), CSR order
__device__ int   g_DEG[NNODES];
__device__ int   g_CUR[NNODES];
__device__ int   g_ROW[NNODES + 1];
__device__ int   g_COL[ETOT];             // src per CSR slot
__device__ int   g_CDST[ETOT];            // dst per CSR slot
__device__ int   g_CSUM[NCHUNK + 1];

// ---------------- helpers ----------------
__device__ __forceinline__ uint32_t f2tf32(float f) {
    uint32_t u;
    asm("cvt.rna.tf32.f32 %0, %1;" : "=r"(u) : "f"(f));
    return u;
}

__device__ __forceinline__ void mma_tf32(float* c, const uint32_t* a, const uint32_t* b) {
    asm volatile(
        "mma.sync.aligned.m16n8k8.row.col.f32.tf32.tf32.f32 "
        "{%0,%1,%2,%3}, {%4,%5,%6,%7}, {%8,%9}, {%0,%1,%2,%3};\n"
        : "+f"(c[0]), "+f"(c[1]), "+f"(c[2]), "+f"(c[3])
        : "r"(a[0]), "r"(a[1]), "r"(a[2]), "r"(a[3]), "r"(b[0]), "r"(b[1]));
}

// ---------------- TF32 tensor-core GEMM, optional fp16 output ---------------
#define ALD 20
#define BLD 136

__global__ __launch_bounds__(256, 2)
void tgemm128(const float* __restrict__ A, const float* __restrict__ B,
              float* __restrict__ C, int M, int Nn, int K,
              const float* __restrict__ bias, int half_out) {
    const int BM = 128, BK = 16;
    __shared__ uint32_t As[2][BM * ALD];
    __shared__ uint32_t Bs[2][BK * BLD];

    int tid  = threadIdx.x;
    int brow = blockIdx.y * BM;
    int bcol = blockIdx.x * 128;
    int w    = tid >> 5, lane = tid & 31;
    int wm   = w & 1, wn = w >> 1;
    int g    = lane >> 2, tg = lane & 3;

    int ar = tid >> 2, ac = (tid & 3) * 4;
    int br = tid >> 5, bc = (tid & 31) * 4;

    const int T = K / BK;
    float acc[4][4][4];
    #pragma unroll
    for (int i = 0; i < 4; i++)
        #pragma unroll
        for (int j = 0; j < 4; j++)
            #pragma unroll
            for (int r = 0; r < 4; r++) acc[i][j][r] = 0.f;

    {
        float4 va0 = make_float4(0.f,0.f,0.f,0.f), va1 = va0;
        long r0 = brow + ar, r1 = brow + ar + 64;
        if (r0 < M) va0 = *reinterpret_cast<const float4*>(A + r0 * K + ac);
        if (r1 < M) va1 = *reinterpret_cast<const float4*>(A + r1 * K + ac);
        uint32_t* d0 = &As[0][ar * ALD + ac];
        d0[0]=f2tf32(va0.x); d0[1]=f2tf32(va0.y); d0[2]=f2tf32(va0.z); d0[3]=f2tf32(va0.w);
        uint32_t* d1 = &As[0][(ar + 64) * ALD + ac];
        d1[0]=f2tf32(va1.x); d1[1]=f2tf32(va1.y); d1[2]=f2tf32(va1.z); d1[3]=f2tf32(va1.w);
        float4 vb0 = *reinterpret_cast<const float4*>(B + (long)br * Nn + bcol + bc);
        float4 vb1 = *reinterpret_cast<const float4*>(B + (long)(br + 8) * Nn + bcol + bc);
        uint32_t* e0 = &Bs[0][br * BLD + bc];
        e0[0]=f2tf32(vb0.x); e0[1]=f2tf32(vb0.y); e0[2]=f2tf32(vb0.z); e0[3]=f2tf32(vb0.w);
        uint32_t* e1 = &Bs[0][(br + 8) * BLD + bc];
        e1[0]=f2tf32(vb1.x); e1[1]=f2tf32(vb1.y); e1[2]=f2tf32(vb1.z); e1[3]=f2tf32(vb1.w);
    }
    __syncthreads();

    for (int t = 0; t < T; t++) {
        int buf = t & 1;
        float4 va0 = make_float4(0.f,0.f,0.f,0.f), va1 = va0, vb0 = va0, vb1 = va0;
        if (t + 1 < T) {
            int k0 = (t + 1) * BK;
            long r0 = brow + ar, r1 = brow + ar + 64;
            if (r0 < M) va0 = *reinterpret_cast<const float4*>(A + r0 * K + k0 + ac);
            if (r1 < M) va1 = *reinterpret_cast<const float4*>(A + r1 * K + k0 + ac);
            vb0 = *reinterpret_cast<const float4*>(B + (long)(k0 + br) * Nn + bcol + bc);
            vb1 = *reinterpret_cast<const float4*>(B + (long)(k0 + br + 8) * Nn + bcol + bc);
        }
        #pragma unroll
        for (int kk = 0; kk < BK; kk += 8) {
            uint32_t af[4][4];
            #pragma unroll
            for (int mt = 0; mt < 4; mt++) {
                int r0 = (wm * 64 + mt * 16 + g) * ALD + kk + tg;
                af[mt][0] = As[buf][r0];
                af[mt][1] = As[buf][r0 + 8 * ALD];
                af[mt][2] = As[buf][r0 + 4];
                af[mt][3] = As[buf][r0 + 8 * ALD + 4];
            }
            uint32_t bf[4][2];
            #pragma unroll
            for (int nt = 0; nt < 4; nt++) {
                int c0 = wn * 32 + nt * 8 + g;
                bf[nt][0] = Bs[buf][(kk + tg) * BLD + c0];
                bf[nt][1] = Bs[buf][(kk + tg + 4) * BLD + c0];
            }
            #pragma unroll
            for (int mt = 0; mt < 4; mt++)
                #pragma unroll
                for (int nt = 0; nt < 4; nt++)
                    mma_tf32(acc[mt][nt], af[mt], bf[nt]);
        }
        if (t + 1 < T) {
            int nb = buf ^ 1;
            uint32_t* d0 = &As[nb][ar * ALD + ac];
            d0[0]=f2tf32(va0.x); d0[1]=f2tf32(va0.y); d0[2]=f2tf32(va0.z); d0[3]=f2tf32(va0.w);
            uint32_t* d1 = &As[nb][(ar + 64) * ALD + ac];
            d1[0]=f2tf32(va1.x); d1[1]=f2tf32(va1.y); d1[2]=f2tf32(va1.z); d1[3]=f2tf32(va1.w);
            uint32_t* e0 = &Bs[nb][br * BLD + bc];
            e0[0]=f2tf32(vb0.x); e0[1]=f2tf32(vb0.y); e0[2]=f2tf32(vb0.z); e0[3]=f2tf32(vb0.w);
            uint32_t* e1 = &Bs[nb][(br + 8) * BLD + bc];
            e1[0]=f2tf32(vb1.x); e1[1]=f2tf32(vb1.y); e1[2]=f2tf32(vb1.z); e1[3]=f2tf32(vb1.w);
            __syncthreads();
        }
    }

    #pragma unroll
    for (int mt = 0; mt < 4; mt++) {
        #pragma unroll
        for (int nt = 0; nt < 4; nt++) {
            int r = brow + wm * 64 + mt * 16 + g;
            int c = bcol + wn * 32 + nt * 8 + tg * 2;
            float bx = 0.f, by = 0.f;
            if (bias) { bx = bias[c]; by = bias[c + 1]; }
            float2 v0 = make_float2(acc[mt][nt][0] + bx, acc[mt][nt][1] + by);
            float2 v1 = make_float2(acc[mt][nt][2] + bx, acc[mt][nt][3] + by);
            if (half_out) {
                __half* Ch = reinterpret_cast<__half*>(C);
                if (r < M)
                    *reinterpret_cast<__half2*>(Ch + (long)r * Nn + c) = __float22half2_rn(v0);
                if (r + 8 < M)
                    *reinterpret_cast<__half2*>(Ch + (long)(r + 8) * Nn + c) = __float22half2_rn(v1);
            } else {
                if (r < M)
                    *reinterpret_cast<float2*>(C + (long)r * Nn + c) = v0;
                if (r + 8 < M)
                    *reinterpret_cast<float2*>(C + (long)(r + 8) * Nn + c) = v1;
            }
        }
    }
}

// ---------------- fold attention vectors into W (both layers, one launch) ---
__global__ void foldw2_k(const float* __restrict__ W1, const float* __restrict__ as1,
                         const float* __restrict__ ad1, float* __restrict__ wsd1,
                         const float* __restrict__ W2, const float* __restrict__ as2,
                         const float* __restrict__ ad2, float* __restrict__ wsd2) {
    int layer = blockIdx.y;
    const float* W   = layer ? W2  : W1;
    const float* as_ = layer ? as2 : as1;
    const float* ad_ = layer ? ad2 : ad1;
    float* wsd = layer ? wsd2 : wsd1;
    int K = layer ? HID : INC;
    int t = blockIdx.x * blockDim.x + threadIdx.x;
    if (t >= K * 8) return;
    int k = t >> 3, j = t & 7, h = j & 3;
    const float* a = ((j < 4) ? as_ : ad_) + h * HID;
    const float* wr = W + (long)k * HH + h * HID;
    float s = 0.f;
    #pragma unroll 16
    for (int c = 0; c < HID; c++) s += wr[c] * a[c];
    wsd[k * 8 + j] = s;
}

// ---------------- skinny scores: es/ed[n][h] = X[n,:] @ Wsd[:,j] ------------
__global__ void sscore_k(const float* __restrict__ X, const float* __restrict__ wsd,
                         float* __restrict__ es, float* __restrict__ ed,
                         int Nn, int K) {
    __shared__ float sW[8][128];
    int tid = threadIdx.x;
    for (int idx = tid; idx < K * 8; idx += blockDim.x) {
        int k = idx >> 3, j = idx & 7;
        sW[j][k] = wsd[k * 8 + j];
    }
    __syncthreads();

    int node = blockIdx.x * 8 + (tid >> 5);
    int lane = tid & 31;
    if (node >= Nn) return;
    int nq = K >> 2;

    float4 xv = make_float4(0.f, 0.f, 0.f, 0.f);
    if (lane < nq)
        xv = reinterpret_cast<const float4*>(X + (long)node * K)[lane];

    float acc[8];
    #pragma unroll
    for (int j = 0; j < 8; j++) {
        float4 wv = make_float4(0.f, 0.f, 0.f, 0.f);
        if (lane < nq)
            wv = *reinterpret_cast<const float4*>(&sW[j][lane * 4]);
        acc[j] = xv.x * wv.x + xv.y * wv.y + xv.z * wv.z + xv.w * wv.w;
    }
    #pragma unroll
    for (int o = 16; o > 0; o >>= 1) {
        #pragma unroll
        for (int j = 0; j < 8; j++)
            acc[j] += __shfl_xor_sync(0xffffffffu, acc[j], o);
    }
    if (lane == 0) {
        *reinterpret_cast<float4*>(es + node * 4) = make_float4(acc[0], acc[1], acc[2], acc[3]);
        *reinterpret_cast<float4*>(ed + node * 4) = make_float4(acc[4], acc[5], acc[6], acc[7]);
    }
}

// ---------------- CSR build ----------------
__global__ void zero2_k(int* __restrict__ a, int* __restrict__ b, int n) {
    int i = blockIdx.x * blockDim.x + threadIdx.x;
    if (i < n) { a[i] = 0; b[i] = 0; }
}

__global__ void deg_k(const int* __restrict__ ei, int* __restrict__ deg,
                      int Ein, int Etot) {
    int e = blockIdx.x * blockDim.x + threadIdx.x;
    if (e >= Etot) return;
    int d = (e < Ein) ? ei[Ein + e] : e - Ein;
    atomicAdd(&deg[d], 1);
}

__global__ void chunksum_k(const int* __restrict__ deg, int* __restrict__ csum, int Nn) {
    __shared__ int wsum[32];
    int t = threadIdx.x, lane = t & 31, wid = t >> 5;
    int i = blockIdx.x * 1024 + t;
    int v = (i < Nn) ? deg[i] : 0;
    #pragma unroll
    for (int o = 16; o > 0; o >>= 1) v += __shfl_xor_sync(0xffffffffu, v, o);
    if (lane == 0) wsum[wid] = v;
    __syncthreads();
    if (wid == 0) {
        int s = wsum[lane];
        #pragma unroll
        for (int o = 16; o > 0; o >>= 1) s += __shfl_xor_sync(0xffffffffu, s, o);
        if (lane == 0) csum[blockIdx.x] = s;
    }
}

__global__ void scanchunks_k(int* __restrict__ csum, int* __restrict__ rowptr,
                             int nchunk, int Nn) {
    int run = 0;
    for (int i = 0; i < nchunk; i++) { int v = csum[i]; csum[i] = run; run += v; }
    csum[nchunk] = run;
    rowptr[Nn] = run;
}

__global__ void rowptr_k(const int* __restrict__ deg, const int* __restrict__ csum,
                         int* __restrict__ rowptr, int Nn) {
    __shared__ int wsum[32];
    int t = threadIdx.x, lane = t & 31, wid = t >> 5;
    int i = blockIdx.x * 1024 + t;
    int v = (i < Nn) ? deg[i] : 0;
    int x = v;
    #pragma unroll
    for (int o = 1; o < 32; o <<= 1) {
        int y = __shfl_up_sync(0xffffffffu, x, o);
        if (lane >= o) x += y;
    }
    if (lane == 31) wsum[wid] = x;
    __syncthreads();
    if (wid == 0) {
        int s = wsum[lane];
        #pragma unroll
        for (int o = 1; o < 32; o <<= 1) {
            int y = __shfl_up_sync(0xffffffffu, s, o);
            if (lane >= o) s += y;
        }
        wsum[lane] = s;
    }
    __syncthreads();
    int off = csum[blockIdx.x] + (wid > 0 ? wsum[wid - 1] : 0);
    if (i < Nn) rowptr[i] = off + x - v;
}

__global__ void fill_k(const int* __restrict__ ei, int* __restrict__ cursor,
                       const int* __restrict__ rowptr, int* __restrict__ colsrc,
                       int* __restrict__ coldst, int Ein, int Etot) {
    int e = blockIdx.x * blockDim.x + threadIdx.x;
    if (e >= Etot) return;
    int s, d;
    if (e < Ein) { s = ei[e]; d = ei[Ein + e]; }
    else         { s = d = e - Ein; }
    int p = atomicAdd(&cursor[d], 1);
    int slot = rowptr[d] + p;
    colsrc[slot] = s;
    coldst[slot] = d;
}

// ---------------- per-edge softmax weights (fp16, CSR order) ----------------
__global__ void edgew_k(const int* __restrict__ colsrc, const int* __restrict__ coldst,
                        const float* __restrict__ es, const float* __restrict__ ed,
                        __half* __restrict__ w4, int Etot) {
    int e = blockIdx.x * blockDim.x + threadIdx.x;
    if (e >= Etot) return;
    int s = colsrc[e], d = coldst[e];
    float4 a = *reinterpret_cast<const float4*>(es + (long)s * 4);
    float4 c = *reinterpret_cast<const float4*>(ed + (long)d * 4);
    float4 r;
    float v;
    v = a.x + c.x; v = (v > 0.f) ? v : 0.2f * v; r.x = __expf(v);
    v = a.y + c.y; v = (v > 0.f) ? v : 0.2f * v; r.y = __expf(v);
    v = a.z + c.z; v = (v > 0.f) ? v : 0.2f * v; r.z = __expf(v);
    v = a.w + c.w; v = (v > 0.f) ? v : 0.2f * v; r.w = __expf(v);
    union { __half2 h[2]; uint2 u; } cv;
    cv.h[0] = __float22half2_rn(make_float2(r.x, r.y));
    cv.h[1] = __float22half2_rn(make_float2(r.z, r.w));
    *reinterpret_cast<uint2*>(w4 + (long)e * 4) = cv.u;
}

// ---------------- fused gather + optional next-layer scores ----------------
// One warp per destination node. Lane L owns 8 consecutive channels of head L/8.
// Only dependent load in the loop is H[s]; weights are linear-address fp16 loads.
// If wsd2 != nullptr, also computes es2/ed2 = out_row @ Wsd2 in the epilogue.
__global__ void gather_k(const __half* __restrict__ H, const int* __restrict__ rowptr,
                         const int* __restrict__ colsrc, const __half* __restrict__ w4,
                         const float* __restrict__ b, const float* __restrict__ g,
                         const float* __restrict__ be, float* __restrict__ out,
                         const float* __restrict__ wsd2, float* __restrict__ es2,
                         float* __restrict__ ed2, int Nn) {
    int warp = (blockIdx.x * blockDim.x + threadIdx.x) >> 5;
    int lane = threadIdx.x & 31;
    if (warp >= Nn) return;
    const int head = lane >> 3;

    float acc[8] = {0.f,0.f,0.f,0.f,0.f,0.f,0.f,0.f};
    float den = 0.f;

    int beg = rowptr[warp], end = rowptr[warp + 1];
    const uint4* __restrict__ H4 = reinterpret_cast<const uint4*>(H);

    int e = beg;
    for (; e + 8 <= end; e += 8) {
        int s[8]; float wv[8];
        #pragma unroll
        for (int u = 0; u < 8; u++) {
            s[u]  = colsrc[e + u];
            wv[u] = __half2float(w4[(long)(e + u) * 4 + head]);
        }
        #pragma unroll
        for (int u = 0; u < 8; u++) {
            uint4 hv = H4[(long)s[u] * 32 + lane];
            const __half2* hp = reinterpret_cast<const __half2*>(&hv);
            float2 f0 = __half22float2(hp[0]);
            float2 f1 = __half22float2(hp[1]);
            float2 f2 = __half22float2(hp[2]);
            float2 f3 = __half22float2(hp[3]);
            den += wv[u];
            acc[0] += wv[u] * f0.x; acc[1] += wv[u] * f0.y;
            acc[2] += wv[u] * f1.x; acc[3] += wv[u] * f1.y;
            acc[4] += wv[u] * f2.x; acc[5] += wv[u] * f2.y;
            acc[6] += wv[u] * f3.x; acc[7] += wv[u] * f3.y;
        }
    }
    for (; e < end; e++) {
        int s0  = colsrc[e];
        float w0 = __half2float(w4[(long)e * 4 + head]);
        uint4 hv = H4[(long)s0 * 32 + lane];
        const __half2* hp = reinterpret_cast<const __half2*>(&hv);
        float2 f0 = __half22float2(hp[0]);
        float2 f1 = __half22float2(hp[1]);
        float2 f2 = __half22float2(hp[2]);
        float2 f3 = __half22float2(hp[3]);
        den += w0;
        acc[0] += w0 * f0.x; acc[1] += w0 * f0.y;
        acc[2] += w0 * f1.x; acc[3] += w0 * f1.y;
        acc[4] += w0 * f2.x; acc[5] += w0 * f2.y;
        acc[6] += w0 * f3.x; acc[7] += w0 * f3.y;
    }

    float r = 1.f / den;
    float v8[8];
    #pragma unroll
    for (int i = 0; i < 8; i++) v8[i] = acc[i] * r;

    // cross-head sum: lanes L, L^8, L^16, L^24 hold same channels, diff heads
    #pragma unroll
    for (int i = 0; i < 8; i++) {
        v8[i] += __shfl_xor_sync(0xffffffffu, v8[i], 8);
        v8[i] += __shfl_xor_sync(0xffffffffu, v8[i], 16);
    }

    int ch = (lane & 7) * 8;
    #pragma unroll
    for (int i = 0; i < 8; i++) v8[i] = v8[i] * 0.25f + b[ch + i];

    float sum = 0.f, ssq = 0.f;
    #pragma unroll
    for (int i = 0; i < 8; i++) { sum += v8[i]; ssq += v8[i] * v8[i]; }
    #pragma unroll
    for (int o = 16; o > 0; o >>= 1) {
        sum += __shfl_xor_sync(0xffffffffu, sum, o);
        ssq += __shfl_xor_sync(0xffffffffu, ssq, o);
    }
    float mean = sum * (1.f / 256.f);
    float var  = ssq * (1.f / 256.f) - mean * mean;
    float inv  = rsqrtf(var + 1e-5f);

    #pragma unroll
    for (int i = 0; i < 8; i++)
        v8[i] = fmaxf((v8[i] - mean) * inv * g[ch + i] + be[ch + i], 0.f);

    if (lane < 8) {
        float4 o0 = make_float4(v8[0], v8[1], v8[2], v8[3]);
        float4 o1 = make_float4(v8[4], v8[5], v8[6], v8[7]);
        float4* op = reinterpret_cast<float4*>(out + (long)warp * HID + ch);
        op[0] = o0; op[1] = o1;
    }

    // ---- fused next-layer scores: es2/ed2 = v8row @ Wsd2 ----
    if (wsd2) {
        float p[8] = {0.f,0.f,0.f,0.f,0.f,0.f,0.f,0.f};
        #pragma unroll
        for (int i = 0; i < 8; i++) {
            float4 lo = *reinterpret_cast<const float4*>(wsd2 + (ch + i) * 8);
            float4 hi = *reinterpret_cast<const float4*>(wsd2 + (ch + i) * 8 + 4);
            p[0] += v8[i] * lo.x; p[1] += v8[i] * lo.y;
            p[2] += v8[i] * lo.z; p[3] += v8[i] * lo.w;
            p[4] += v8[i] * hi.x; p[5] += v8[i] * hi.y;
            p[6] += v8[i] * hi.z; p[7] += v8[i] * hi.w;
        }
        #pragma unroll
        for (int o = 4; o > 0; o >>= 1) {
            #pragma unroll
            for (int j = 0; j < 8; j++)
                p[j] += __shfl_xor_sync(0xffffffffu, p[j], o);
        }
        if (lane == 0) {
            *reinterpret_cast<float4*>(es2 + (long)warp * 4) = make_float4(p[0], p[1], p[2], p[3]);
            *reinterpret_cast<float4*>(ed2 + (long)warp * 4) = make_float4(p[4], p[5], p[6], p[7]);
        }
    }
}

// ---------------------------------------------------------------------------
extern "C" void kernel_launch(void* const* d_in, const int* in_sizes, int n_in,
                              void* d_out, int out_size) {
    const float* x     = (const float*)d_in[0];
    const int*   ei    = (const int*)  d_in[1];
    const float* W1    = (const float*)d_in[2];
    const float* asrc1 = (const float*)d_in[3];
    const float* adst1 = (const float*)d_in[4];
    const float* b1    = (const float*)d_in[5];
    const float* g1    = (const float*)d_in[6];
    const float* be1   = (const float*)d_in[7];
    const float* W2    = (const float*)d_in[8];
    const float* asrc2 = (const float*)d_in[9];
    const float* adst2 = (const float*)d_in[10];
    const float* b2    = (const float*)d_in[11];
    const float* g2    = (const float*)d_in[12];
    const float* be2   = (const float*)d_in[13];
    const float* Wo    = (const float*)d_in[14];
    const float* bo    = (const float*)d_in[15];
    float* out = (float*)d_out;

    const int Nn   = in_sizes[0] / INC;      // 50000
    const int Ein  = in_sizes[1] / 2;        // 800000
    const int Etot = Ein + Nn;               // 850000
    const int nchunk = (Nn + 1023) / 1024;

    __half *H, *W4;
    float *ES, *ED, *F1, *F2, *WSD1, *WSD2;
    int *DEG, *CUR, *ROW, *COL, *CDST, *CSUM;
    cudaGetSymbolAddress((void**)&H,    g_H);
    cudaGetSymbolAddress((void**)&ES,   g_ES);
    cudaGetSymbolAddress((void**)&ED,   g_ED);
    cudaGetSymbolAddress((void**)&F1,   g_F1);
    cudaGetSymbolAddress((void**)&F2,   g_F2);
    cudaGetSymbolAddress((void**)&WSD1, g_WSD1);
    cudaGetSymbolAddress((void**)&WSD2, g_WSD2);
    cudaGetSymbolAddress((void**)&W4,   g_W4);
    cudaGetSymbolAddress((void**)&DEG,  g_DEG);
    cudaGetSymbolAddress((void**)&CUR,  g_CUR);
    cudaGetSymbolAddress((void**)&ROW,  g_ROW);
    cudaGetSymbolAddress((void**)&COL,  g_COL);
    cudaGetSymbolAddress((void**)&CDST, g_CDST);
    cudaGetSymbolAddress((void**)&CSUM, g_CSUM);

    dim3 gemm1_grid(HH / 128, (Nn + 127) / 128);
    dim3 gemm2_grid(HH / 128, (Nn + 127) / 128);
    dim3 gemmo_grid(OUTC / 128, (Nn + 127) / 128);
    int edge_blocks  = (Etot + 255) / 256;
    int node_warpblk = (Nn * 32 + 255) / 256;
    int score_blocks = (Nn + 7) / 8;
    dim3 fold_grid((INC * 8 + 255) / 256, 2);

    // ---------------- CSR build + weight folds ----------------
    zero2_k<<<(Nn + 1023) / 1024, 1024>>>(DEG, CUR, Nn);
    deg_k<<<edge_blocks, 256>>>(ei, DEG, Ein, Etot);
    chunksum_k<<<nchunk, 1024>>>(DEG, CSUM, Nn);
    scanchunks_k<<<1, 1>>>(CSUM, ROW, nchunk, Nn);
    rowptr_k<<<nchunk, 1024>>>(DEG, CSUM, ROW, Nn);
    fill_k<<<edge_blocks, 256>>>(ei, CUR, ROW, COL, CDST, Ein, Etot);
    foldw2_k<<<fold_grid, 256>>>(W1, asrc1, adst1, WSD1, W2, asrc2, adst2, WSD2);

    // ---------------- layer 1 ----------------
    sscore_k<<<score_blocks, 256>>>(x, WSD1, ES, ED, Nn, INC);
    tgemm128<<<gemm1_grid, 256>>>(x, W1, (float*)H, Nn, HH, INC, nullptr, 1);
    edgew_k<<<edge_blocks, 256>>>(COL, CDST, ES, ED, W4, Etot);
    // gather1 writes F1 AND layer-2 scores (overwrites ES/ED after edgew1 used them)
    gather_k<<<node_warpblk, 256>>>(H, ROW, COL, W4, b1, g1, be1, F1,
                                    WSD2, ES, ED, Nn);

    // ---------------- layer 2 ----------------
    tgemm128<<<gemm2_grid, 256>>>(F1, W2, (float*)H, Nn, HH, HID, nullptr, 1);
    edgew_k<<<edge_blocks, 256>>>(COL, CDST, ES, ED, W4, Etot);
    gather_k<<<node_warpblk, 256>>>(H, ROW, COL, W4, b2, g2, be2, F2,
                                    nullptr, nullptr, nullptr, Nn);

    // ---------------- output projection (fp32 out) ----------------
    tgemm128<<<gemmo_grid, 256>>>(F2, Wo, out, Nn, OUTC, HID, bo, 0);
}

// round 10
// speedup vs baseline: 1.2959x; 1.2959x over previous
#include <cuda_runtime.h>
#include <cuda_fp16.h>
#include <cstdint>

#define NNODES 50000
#define NEDGES 800000
#define ETOT   (NNODES + NEDGES)
#define HEADS  4
#define HID    64
#define HH     256   // HEADS*HID
#define INC    128
#define OUTC   128
#define NCHUNK ((NNODES + 1023) / 1024)

// ---------------- scratch (device globals; no allocation) ----------------
__device__ __half g_H [NNODES * HH];      // transformed features, fp16 [N,4,64]
__device__ float g_ES  [NNODES * HEADS];
__device__ float g_ED  [NNODES * HEADS];
__device__ float g_F1  [NNODES * HID];
__device__ float g_F2  [NNODES * HID];
__device__ float g_WSD1[INC * 8];
__device__ float g_WSD2[HID * 8];
__device__ __half g_W4 [(size_t)ETOT * HEADS];   // per-edge weights (fp16), CSR order
__device__ int   g_DEG[NNODES];
__device__ int   g_CUR[NNODES];
__device__ int   g_ROW[NNODES + 1];
__device__ int   g_COL[ETOT];             // src per CSR slot
__device__ int   g_CDST[ETOT];            // dst per CSR slot
__device__ int   g_CSUM[NCHUNK + 1];

// ---------------- helpers ----------------
__device__ __forceinline__ uint32_t f2tf32(float f) {
    uint32_t u;
    asm("cvt.rna.tf32.f32 %0, %1;" : "=r"(u) : "f"(f));
    return u;
}

__device__ __forceinline__ void mma_tf32(float* c, const uint32_t* a, const uint32_t* b) {
    asm volatile(
        "mma.sync.aligned.m16n8k8.row.col.f32.tf32.tf32.f32 "
        "{%0,%1,%2,%3}, {%4,%5,%6,%7}, {%8,%9}, {%0,%1,%2,%3};\n"
        : "+f"(c[0]), "+f"(c[1]), "+f"(c[2]), "+f"(c[3])
        : "r"(a[0]), "r"(a[1]), "r"(a[2]), "r"(a[3]), "r"(b[0]), "r"(b[1]));
}

// ---------------- TF32 tensor-core GEMM, optional fp16 output ---------------
#define ALD 20
#define BLD 136

__global__ __launch_bounds__(256, 2)
void tgemm128(const float* __restrict__ A, const float* __restrict__ B,
              float* __restrict__ C, int M, int Nn, int K,
              const float* __restrict__ bias, int half_out) {
    const int BM = 128, BK = 16;
    __shared__ uint32_t As[2][BM * ALD];
    __shared__ uint32_t Bs[2][BK * BLD];

    int tid  = threadIdx.x;
    int brow = blockIdx.y * BM;
    int bcol = blockIdx.x * 128;
    int w    = tid >> 5, lane = tid & 31;
    int wm   = w & 1, wn = w >> 1;
    int g    = lane >> 2, tg = lane & 3;

    int ar = tid >> 2, ac = (tid & 3) * 4;
    int br = tid >> 5, bc = (tid & 31) * 4;

    const int T = K / BK;
    float acc[4][4][4];
    #pragma unroll
    for (int i = 0; i < 4; i++)
        #pragma unroll
        for (int j = 0; j < 4; j++)
            #pragma unroll
            for (int r = 0; r < 4; r++) acc[i][j][r] = 0.f;

    {
        float4 va0 = make_float4(0.f,0.f,0.f,0.f), va1 = va0;
        long r0 = brow + ar, r1 = brow + ar + 64;
        if (r0 < M) va0 = *reinterpret_cast<const float4*>(A + r0 * K + ac);
        if (r1 < M) va1 = *reinterpret_cast<const float4*>(A + r1 * K + ac);
        uint32_t* d0 = &As[0][ar * ALD + ac];
        d0[0]=f2tf32(va0.x); d0[1]=f2tf32(va0.y); d0[2]=f2tf32(va0.z); d0[3]=f2tf32(va0.w);
        uint32_t* d1 = &As[0][(ar + 64) * ALD + ac];
        d1[0]=f2tf32(va1.x); d1[1]=f2tf32(va1.y); d1[2]=f2tf32(va1.z); d1[3]=f2tf32(va1.w);
        float4 vb0 = *reinterpret_cast<const float4*>(B + (long)br * Nn + bcol + bc);
        float4 vb1 = *reinterpret_cast<const float4*>(B + (long)(br + 8) * Nn + bcol + bc);
        uint32_t* e0 = &Bs[0][br * BLD + bc];
        e0[0]=f2tf32(vb0.x); e0[1]=f2tf32(vb0.y); e0[2]=f2tf32(vb0.z); e0[3]=f2tf32(vb0.w);
        uint32_t* e1 = &Bs[0][(br + 8) * BLD + bc];
        e1[0]=f2tf32(vb1.x); e1[1]=f2tf32(vb1.y); e1[2]=f2tf32(vb1.z); e1[3]=f2tf32(vb1.w);
    }
    __syncthreads();

    for (int t = 0; t < T; t++) {
        int buf = t & 1;
        float4 va0 = make_float4(0.f,0.f,0.f,0.f), va1 = va0, vb0 = va0, vb1 = va0;
        if (t + 1 < T) {
            int k0 = (t + 1) * BK;
            long r0 = brow + ar, r1 = brow + ar + 64;
            if (r0 < M) va0 = *reinterpret_cast<const float4*>(A + r0 * K + k0 + ac);
            if (r1 < M) va1 = *reinterpret_cast<const float4*>(A + r1 * K + k0 + ac);
            vb0 = *reinterpret_cast<const float4*>(B + (long)(k0 + br) * Nn + bcol + bc);
            vb1 = *reinterpret_cast<const float4*>(B + (long)(k0 + br + 8) * Nn + bcol + bc);
        }
        #pragma unroll
        for (int kk = 0; kk < BK; kk += 8) {
            uint32_t af[4][4];
            #pragma unroll
            for (int mt = 0; mt < 4; mt++) {
                int r0 = (wm * 64 + mt * 16 + g) * ALD + kk + tg;
                af[mt][0] = As[buf][r0];
                af[mt][1] = As[buf][r0 + 8 * ALD];
                af[mt][2] = As[buf][r0 + 4];
                af[mt][3] = As[buf][r0 + 8 * ALD + 4];
            }
            uint32_t bf[4][2];
            #pragma unroll
            for (int nt = 0; nt < 4; nt++) {
                int c0 = wn * 32 + nt * 8 + g;
                bf[nt][0] = Bs[buf][(kk + tg) * BLD + c0];
                bf[nt][1] = Bs[buf][(kk + tg + 4) * BLD + c0];
            }
            #pragma unroll
            for (int mt = 0; mt < 4; mt++)
                #pragma unroll
                for (int nt = 0; nt < 4; nt++)
                    mma_tf32(acc[mt][nt], af[mt], bf[nt]);
        }
        if (t + 1 < T) {
            int nb = buf ^ 1;
            uint32_t* d0 = &As[nb][ar * ALD + ac];
            d0[0]=f2tf32(va0.x); d0[1]=f2tf32(va0.y); d0[2]=f2tf32(va0.z); d0[3]=f2tf32(va0.w);
            uint32_t* d1 = &As[nb][(ar + 64) * ALD + ac];
            d1[0]=f2tf32(va1.x); d1[1]=f2tf32(va1.y); d1[2]=f2tf32(va1.z); d1[3]=f2tf32(va1.w);
            uint32_t* e0 = &Bs[nb][br * BLD + bc];
            e0[0]=f2tf32(vb0.x); e0[1]=f2tf32(vb0.y); e0[2]=f2tf32(vb0.z); e0[3]=f2tf32(vb0.w);
            uint32_t* e1 = &Bs[nb][(br + 8) * BLD + bc];
            e1[0]=f2tf32(vb1.x); e1[1]=f2tf32(vb1.y); e1[2]=f2tf32(vb1.z); e1[3]=f2tf32(vb1.w);
            __syncthreads();
        }
    }

    #pragma unroll
    for (int mt = 0; mt < 4; mt++) {
        #pragma unroll
        for (int nt = 0; nt < 4; nt++) {
            int r = brow + wm * 64 + mt * 16 + g;
            int c = bcol + wn * 32 + nt * 8 + tg * 2;
            float bx = 0.f, by = 0.f;
            if (bias) { bx = bias[c]; by = bias[c + 1]; }
            float2 v0 = make_float2(acc[mt][nt][0] + bx, acc[mt][nt][1] + by);
            float2 v1 = make_float2(acc[mt][nt][2] + bx, acc[mt][nt][3] + by);
            if (half_out) {
                __half* Ch = reinterpret_cast<__half*>(C);
                if (r < M)
                    *reinterpret_cast<__half2*>(Ch + (long)r * Nn + c) = __float22half2_rn(v0);
                if (r + 8 < M)
                    *reinterpret_cast<__half2*>(Ch + (long)(r + 8) * Nn + c) = __float22half2_rn(v1);
            } else {
                if (r < M)
                    *reinterpret_cast<float2*>(C + (long)r * Nn + c) = v0;
                if (r + 8 < M)
                    *reinterpret_cast<float2*>(C + (long)(r + 8) * Nn + c) = v1;
            }
        }
    }
}

// ---------------- fold attention vectors into W (both layers, one launch) ---
__global__ void foldw2_k(const float* __restrict__ W1, const float* __restrict__ as1,
                         const float* __restrict__ ad1, float* __restrict__ wsd1,
                         const float* __restrict__ W2, const float* __restrict__ as2,
                         const float* __restrict__ ad2, float* __restrict__ wsd2) {
    int layer = blockIdx.y;
    const float* W   = layer ? W2  : W1;
    const float* as_ = layer ? as2 : as1;
    const float* ad_ = layer ? ad2 : ad1;
    float* wsd = layer ? wsd2 : wsd1;
    int K = layer ? HID : INC;
    int t = blockIdx.x * blockDim.x + threadIdx.x;
    if (t >= K * 8) return;
    int k = t >> 3, j = t & 7, h = j & 3;
    const float* a = ((j < 4) ? as_ : ad_) + h * HID;
    const float* wr = W + (long)k * HH + h * HID;
    float s = 0.f;
    #pragma unroll 16
    for (int c = 0; c < HID; c++) s += wr[c] * a[c];
    wsd[k * 8 + j] = s;
}

// ---------------- skinny scores: es/ed[n][h] = X[n,:] @ Wsd[:,j] ------------
__global__ void sscore_k(const float* __restrict__ X, const float* __restrict__ wsd,
                         float* __restrict__ es, float* __restrict__ ed,
                         int Nn, int K) {
    __shared__ float sW[8][128];
    int tid = threadIdx.x;
    for (int idx = tid; idx < K * 8; idx += blockDim.x) {
        int k = idx >> 3, j = idx & 7;
        sW[j][k] = wsd[k * 8 + j];
    }
    __syncthreads();

    int node = blockIdx.x * 8 + (tid >> 5);
    int lane = tid & 31;
    if (node >= Nn) return;
    int nq = K >> 2;

    float4 xv = make_float4(0.f, 0.f, 0.f, 0.f);
    if (lane < nq)
        xv = reinterpret_cast<const float4*>(X + (long)node * K)[lane];

    float acc[8];
    #pragma unroll
    for (int j = 0; j < 8; j++) {
        float4 wv = make_float4(0.f, 0.f, 0.f, 0.f);
        if (lane < nq)
            wv = *reinterpret_cast<const float4*>(&sW[j][lane * 4]);
        acc[j] = xv.x * wv.x + xv.y * wv.y + xv.z * wv.z + xv.w * wv.w;
    }
    #pragma unroll
    for (int o = 16; o > 0; o >>= 1) {
        #pragma unroll
        for (int j = 0; j < 8; j++)
            acc[j] += __shfl_xor_sync(0xffffffffu, acc[j], o);
    }
    if (lane == 0) {
        *reinterpret_cast<float4*>(es + node * 4) = make_float4(acc[0], acc[1], acc[2], acc[3]);
        *reinterpret_cast<float4*>(ed + node * 4) = make_float4(acc[4], acc[5], acc[6], acc[7]);
    }
}

// ---------------- CSR build ----------------
__global__ void zero2_k(int* __restrict__ a, int* __restrict__ b, int n) {
    int i = blockIdx.x * blockDim.x + threadIdx.x;
    if (i < n) { a[i] = 0; b[i] = 0; }
}

__global__ void deg_k(const int* __restrict__ ei, int* __restrict__ deg,
                      int Ein, int Etot) {
    int e = blockIdx.x * blockDim.x + threadIdx.x;
    if (e >= Etot) return;
    int d = (e < Ein) ? ei[Ein + e] : e - Ein;
    atomicAdd(&deg[d], 1);
}

__global__ void chunksum_k(const int* __restrict__ deg, int* __restrict__ csum, int Nn) {
    __shared__ int wsum[32];
    int t = threadIdx.x, lane = t & 31, wid = t >> 5;
    int i = blockIdx.x * 1024 + t;
    int v = (i < Nn) ? deg[i] : 0;
    #pragma unroll
    for (int o = 16; o > 0; o >>= 1) v += __shfl_xor_sync(0xffffffffu, v, o);
    if (lane == 0) wsum[wid] = v;
    __syncthreads();
    if (wid == 0) {
        int s = wsum[lane];
        #pragma unroll
        for (int o = 16; o > 0; o >>= 1) s += __shfl_xor_sync(0xffffffffu, s, o);
        if (lane == 0) csum[blockIdx.x] = s;
    }
}

__global__ void scanchunks_k(int* __restrict__ csum, int* __restrict__ rowptr,
                             int nchunk, int Nn) {
    int run = 0;
    for (int i = 0; i < nchunk; i++) { int v = csum[i]; csum[i] = run; run += v; }
    csum[nchunk] = run;
    rowptr[Nn] = run;
}

__global__ void rowptr_k(const int* __restrict__ deg, const int* __restrict__ csum,
                         int* __restrict__ rowptr, int Nn) {
    __shared__ int wsum[32];
    int t = threadIdx.x, lane = t & 31, wid = t >> 5;
    int i = blockIdx.x * 1024 + t;
    int v = (i < Nn) ? deg[i] : 0;
    int x = v;
    #pragma unroll
    for (int o = 1; o < 32; o <<= 1) {
        int y = __shfl_up_sync(0xffffffffu, x, o);
        if (lane >= o) x += y;
    }
    if (lane == 31) wsum[wid] = x;
    __syncthreads();
    if (wid == 0) {
        int s = wsum[lane];
        #pragma unroll
        for (int o = 1; o < 32; o <<= 1) {
            int y = __shfl_up_sync(0xffffffffu, s, o);
            if (lane >= o) s += y;
        }
        wsum[lane] = s;
    }
    __syncthreads();
    int off = csum[blockIdx.x] + (wid > 0 ? wsum[wid - 1] : 0);
    if (i < Nn) rowptr[i] = off + x - v;
}

__global__ void fill_k(const int* __restrict__ ei, int* __restrict__ cursor,
                       const int* __restrict__ rowptr, int* __restrict__ colsrc,
                       int* __restrict__ coldst, int Ein, int Etot) {
    int e = blockIdx.x * blockDim.x + threadIdx.x;
    if (e >= Etot) return;
    int s, d;
    if (e < Ein) { s = ei[e]; d = ei[Ein + e]; }
    else         { s = d = e - Ein; }
    int p = atomicAdd(&cursor[d], 1);
    int slot = rowptr[d] + p;
    colsrc[slot] = s;
    coldst[slot] = d;
}

// ---------------- per-edge softmax weights (fp16, CSR order) ----------------
__global__ void edgew_k(const int* __restrict__ colsrc, const int* __restrict__ coldst,
                        const float* __restrict__ es, const float* __restrict__ ed,
                        __half* __restrict__ w4, int Etot) {
    int e = blockIdx.x * blockDim.x + threadIdx.x;
    if (e >= Etot) return;
    int s = colsrc[e], d = coldst[e];
    float4 a = *reinterpret_cast<const float4*>(es + (long)s * 4);
    float4 c = *reinterpret_cast<const float4*>(ed + (long)d * 4);
    float4 r;
    float v;
    v = a.x + c.x; v = (v > 0.f) ? v : 0.2f * v; r.x = __expf(v);
    v = a.y + c.y; v = (v > 0.f) ? v : 0.2f * v; r.y = __expf(v);
    v = a.z + c.z; v = (v > 0.f) ? v : 0.2f * v; r.z = __expf(v);
    v = a.w + c.w; v = (v > 0.f) ? v : 0.2f * v; r.w = __expf(v);
    union { __half2 h[2]; uint2 u; } cv;
    cv.h[0] = __float22half2_rn(make_float2(r.x, r.y));
    cv.h[1] = __float22half2_rn(make_float2(r.z, r.w));
    *reinterpret_cast<uint2*>(w4 + (long)e * 4) = cv.u;
}

// ---------------- fused gather (fp16 H, fp16 weights; lean registers) -------
// One warp per destination node. Lane L owns 8 consecutive channels of head L/8.
// Only dependent load in the loop is H[s]; weights are linear-address fp16 loads.
__global__ void gather_k(const __half* __restrict__ H, const int* __restrict__ rowptr,
                         const int* __restrict__ colsrc, const __half* __restrict__ w4,
                         const float* __restrict__ b, const float* __restrict__ g,
                         const float* __restrict__ be,
                         float* __restrict__ out, int Nn) {
    int warp = (blockIdx.x * blockDim.x + threadIdx.x) >> 5;
    int lane = threadIdx.x & 31;
    if (warp >= Nn) return;
    const int head = lane >> 3;

    float acc[8] = {0.f,0.f,0.f,0.f,0.f,0.f,0.f,0.f};
    float den = 0.f;

    int beg = rowptr[warp], end = rowptr[warp + 1];
    const uint4* __restrict__ H4 = reinterpret_cast<const uint4*>(H);

    int e = beg;
    for (; e + 8 <= end; e += 8) {
        int s[8]; float wv[8];
        #pragma unroll
        for (int u = 0; u < 8; u++) {
            s[u]  = colsrc[e + u];
            wv[u] = __half2float(w4[(long)(e + u) * 4 + head]);
        }
        #pragma unroll
        for (int u = 0; u < 8; u++) {
            uint4 hv = H4[(long)s[u] * 32 + lane];
            const __half2* hp = reinterpret_cast<const __half2*>(&hv);
            float2 f0 = __half22float2(hp[0]);
            float2 f1 = __half22float2(hp[1]);
            float2 f2 = __half22float2(hp[2]);
            float2 f3 = __half22float2(hp[3]);
            den += wv[u];
            acc[0] += wv[u] * f0.x; acc[1] += wv[u] * f0.y;
            acc[2] += wv[u] * f1.x; acc[3] += wv[u] * f1.y;
            acc[4] += wv[u] * f2.x; acc[5] += wv[u] * f2.y;
            acc[6] += wv[u] * f3.x; acc[7] += wv[u] * f3.y;
        }
    }
    for (; e < end; e++) {
        int s0  = colsrc[e];
        float w0 = __half2float(w4[(long)e * 4 + head]);
        uint4 hv = H4[(long)s0 * 32 + lane];
        const __half2* hp = reinterpret_cast<const __half2*>(&hv);
        float2 f0 = __half22float2(hp[0]);
        float2 f1 = __half22float2(hp[1]);
        float2 f2 = __half22float2(hp[2]);
        float2 f3 = __half22float2(hp[3]);
        den += w0;
        acc[0] += w0 * f0.x; acc[1] += w0 * f0.y;
        acc[2] += w0 * f1.x; acc[3] += w0 * f1.y;
        acc[4] += w0 * f2.x; acc[5] += w0 * f2.y;
        acc[6] += w0 * f3.x; acc[7] += w0 * f3.y;
    }

    float r = 1.f / den;     // den = full per-head denominator (broadcast weights)
    float v8[8];
    #pragma unroll
    for (int i = 0; i < 8; i++) v8[i] = acc[i] * r;

    // cross-head sum: lanes L, L^8, L^16, L^24 hold same channels, diff heads
    #pragma unroll
    for (int i = 0; i < 8; i++) {
        v8[i] += __shfl_xor_sync(0xffffffffu, v8[i], 8);
        v8[i] += __shfl_xor_sync(0xffffffffu, v8[i], 16);
    }

    int ch = (lane & 7) * 8;
    #pragma unroll
    for (int i = 0; i < 8; i++) v8[i] = v8[i] * 0.25f + b[ch + i];

    float sum = 0.f, ssq = 0.f;
    #pragma unroll
    for (int i = 0; i < 8; i++) { sum += v8[i]; ssq += v8[i] * v8[i]; }
    #pragma unroll
    for (int o = 16; o > 0; o >>= 1) {
        sum += __shfl_xor_sync(0xffffffffu, sum, o);
        ssq += __shfl_xor_sync(0xffffffffu, ssq, o);
    }
    float mean = sum * (1.f / 256.f);
    float var  = ssq * (1.f / 256.f) - mean * mean;
    float inv  = rsqrtf(var + 1e-5f);

    #pragma unroll
    for (int i = 0; i < 8; i++)
        v8[i] = fmaxf((v8[i] - mean) * inv * g[ch + i] + be[ch + i], 0.f);

    if (lane < 8) {
        float4 o0 = make_float4(v8[0], v8[1], v8[2], v8[3]);
        float4 o1 = make_float4(v8[4], v8[5], v8[6], v8[7]);
        float4* op = reinterpret_cast<float4*>(out + (long)warp * HID + ch);
        op[0] = o0; op[1] = o1;
    }
}

// ---------------------------------------------------------------------------
extern "C" void kernel_launch(void* const* d_in, const int* in_sizes, int n_in,
                              void* d_out, int out_size) {
    const float* x     = (const float*)d_in[0];
    const int*   ei    = (const int*)  d_in[1];
    const float* W1    = (const float*)d_in[2];
    const float* asrc1 = (const float*)d_in[3];
    const float* adst1 = (const float*)d_in[4];
    const float* b1    = (const float*)d_in[5];
    const float* g1    = (const float*)d_in[6];
    const float* be1   = (const float*)d_in[7];
    const float* W2    = (const float*)d_in[8];
    const float* asrc2 = (const float*)d_in[9];
    const float* adst2 = (const float*)d_in[10];
    const float* b2    = (const float*)d_in[11];
    const float* g2    = (const float*)d_in[12];
    const float* be2   = (const float*)d_in[13];
    const float* Wo    = (const float*)d_in[14];
    const float* bo    = (const float*)d_in[15];
    float* out = (float*)d_out;

    const int Nn   = in_sizes[0] / INC;      // 50000
    const int Ein  = in_sizes[1] / 2;        // 800000
    const int Etot = Ein + Nn;               // 850000
    const int nchunk = (Nn + 1023) / 1024;

    __half *H, *W4;
    float *ES, *ED, *F1, *F2, *WSD1, *WSD2;
    int *DEG, *CUR, *ROW, *COL, *CDST, *CSUM;
    cudaGetSymbolAddress((void**)&H,    g_H);
    cudaGetSymbolAddress((void**)&ES,   g_ES);
    cudaGetSymbolAddress((void**)&ED,   g_ED);
    cudaGetSymbolAddress((void**)&F1,   g_F1);
    cudaGetSymbolAddress((void**)&F2,   g_F2);
    cudaGetSymbolAddress((void**)&WSD1, g_WSD1);
    cudaGetSymbolAddress((void**)&WSD2, g_WSD2);
    cudaGetSymbolAddress((void**)&W4,   g_W4);
    cudaGetSymbolAddress((void**)&DEG,  g_DEG);
    cudaGetSymbolAddress((void**)&CUR,  g_CUR);
    cudaGetSymbolAddress((void**)&ROW,  g_ROW);
    cudaGetSymbolAddress((void**)&COL,  g_COL);
    cudaGetSymbolAddress((void**)&CDST, g_CDST);
    cudaGetSymbolAddress((void**)&CSUM, g_CSUM);

    dim3 gemm1_grid(HH / 128, (Nn + 127) / 128);
    dim3 gemm2_grid(HH / 128, (Nn + 127) / 128);
    dim3 gemmo_grid(OUTC / 128, (Nn + 127) / 128);
    int edge_blocks  = (Etot + 255) / 256;
    int node_warpblk = (Nn * 32 + 255) / 256;
    int score_blocks = (Nn + 7) / 8;
    dim3 fold_grid((INC * 8 + 255) / 256, 2);

    // ---------------- CSR build + weight folds ----------------
    zero2_k<<<(Nn + 1023) / 1024, 1024>>>(DEG, CUR, Nn);
    deg_k<<<edge_blocks, 256>>>(ei, DEG, Ein, Etot);
    chunksum_k<<<nchunk, 1024>>>(DEG, CSUM, Nn);
    scanchunks_k<<<1, 1>>>(CSUM, ROW, nchunk, Nn);
    rowptr_k<<<nchunk, 1024>>>(DEG, CSUM, ROW, Nn);
    fill_k<<<edge_blocks, 256>>>(ei, CUR, ROW, COL, CDST, Ein, Etot);
    foldw2_k<<<fold_grid, 256>>>(W1, asrc1, adst1, WSD1, W2, asrc2, adst2, WSD2);

    // ---------------- layer 1 ----------------
    sscore_k<<<score_blocks, 256>>>(x, WSD1, ES, ED, Nn, INC);
    tgemm128<<<gemm1_grid, 256>>>(x, W1, (float*)H, Nn, HH, INC, nullptr, 1);
    edgew_k<<<edge_blocks, 256>>>(COL, CDST, ES, ED, W4, Etot);
    gather_k<<<node_warpblk, 256>>>(H, ROW, COL, W4, b1, g1, be1, F1, Nn);

    // ---------------- layer 2 ----------------
    sscore_k<<<score_blocks, 256>>>(F1, WSD2, ES, ED, Nn, HID);
    tgemm128<<<gemm2_grid, 256>>>(F1, W2, (float*)H, Nn, HH, HID, nullptr, 1);
    edgew_k<<<edge_blocks, 256>>>(COL, CDST, ES, ED, W4, Etot);
    gather_k<<<node_warpblk, 256>>>(H, ROW, COL, W4, b2, g2, be2, F2, Nn);

    // ---------------- output projection (fp32 out) ----------------
    tgemm128<<<gemmo_grid, 256>>>(F2, Wo, out, Nn, OUTC, HID, bo, 0);
}